// round 3
// baseline (speedup 1.0000x reference)
#include <cuda_runtime.h>
#include <mma.h>
#include <math.h>

using namespace nvcuda;

#define S_LEN 2048
#define D_MODEL 2048
#define N_H 16
#define N_KV 4
#define H_DIM 128
#define SCALING 0.08838834764831845f
#define DM0 0.9779029130879204f

// Scratch (allocation-free rule: __device__ globals)
__device__ float g_q[(size_t)S_LEN * N_H * H_DIM];
__device__ float g_k[(size_t)S_LEN * N_KV * H_DIM];
__device__ float g_v[(size_t)S_LEN * N_KV * H_DIM];
__device__ float g_ctx[(size_t)S_LEN * N_H * H_DIM];
__device__ float g_attn[(size_t)N_H * S_LEN * S_LEN];

// Split one loaded fragment (raw fp32 values) into hi/lo tf32 fragments.
template <typename Frag>
__device__ __forceinline__ void split_frag(const Frag& raw, Frag& hi, Frag& lo)
{
#pragma unroll
    for (int t = 0; t < raw.num_elements; t++) {
        float v = raw.x[t];
        float h = wmma::__float_to_tf32(v);
        hi.x[t] = h;
        lo.x[t] = wmma::__float_to_tf32(v - h);
    }
}

// ---------------------------------------------------------------------------
// 3xTF32 WMMA NT GEMM: C[M,N] = A[M,K] * B[N,K]^T (row-major A,B), fp32 accum.
// BM=BN=128, BK=16, 256 threads (8 warps; warp tile 32m x 64n).
// ---------------------------------------------------------------------------
__global__ void __launch_bounds__(256) wgemm_nt(
    const float* __restrict__ A, const float* __restrict__ B,
    float* __restrict__ C, int M, int N, int K)
{
    __shared__ float As[128][20];
    __shared__ float Bs[128][20];

    const int tid = threadIdx.x;
    const int warp = tid >> 5;
    const int wm = warp & 3;
    const int wn = warp >> 2;
    const int mBase = blockIdx.y * 128;
    const int nBase = blockIdx.x * 128;

    const int lr = tid >> 1;
    const int lc = (tid & 1) * 8;

    wmma::fragment<wmma::accumulator, 16, 16, 8, float> acc[2][4];
#pragma unroll
    for (int i = 0; i < 2; i++)
#pragma unroll
        for (int j = 0; j < 4; j++) wmma::fill_fragment(acc[i][j], 0.0f);

    const float* Ap = A + (size_t)(mBase + lr) * K + lc;
    const float* Bp = B + (size_t)(nBase + lr) * K + lc;

    for (int k0 = 0; k0 < K; k0 += 16) {
        float4 a0 = *(const float4*)(Ap + k0);
        float4 a1 = *(const float4*)(Ap + k0 + 4);
        float4 b0 = *(const float4*)(Bp + k0);
        float4 b1 = *(const float4*)(Bp + k0 + 4);
        __syncthreads();
        *(float4*)&As[lr][lc]     = a0; *(float4*)&As[lr][lc + 4] = a1;
        *(float4*)&Bs[lr][lc]     = b0; *(float4*)&Bs[lr][lc + 4] = b1;
        __syncthreads();
#pragma unroll
        for (int ks = 0; ks < 16; ks += 8) {
            wmma::fragment<wmma::matrix_a, 16, 16, 8, wmma::precision::tf32, wmma::row_major> ah[2], al[2];
            wmma::fragment<wmma::matrix_b, 16, 16, 8, wmma::precision::tf32, wmma::col_major> bh[4], bl[4];
#pragma unroll
            for (int i = 0; i < 2; i++) {
                wmma::fragment<wmma::matrix_a, 16, 16, 8, wmma::precision::tf32, wmma::row_major> raw;
                wmma::load_matrix_sync(raw, &As[wm * 32 + i * 16][ks], 20);
                split_frag(raw, ah[i], al[i]);
            }
#pragma unroll
            for (int j = 0; j < 4; j++) {
                wmma::fragment<wmma::matrix_b, 16, 16, 8, wmma::precision::tf32, wmma::col_major> raw;
                wmma::load_matrix_sync(raw, &Bs[wn * 64 + j * 16][ks], 20);
                split_frag(raw, bh[j], bl[j]);
            }
#pragma unroll
            for (int i = 0; i < 2; i++)
#pragma unroll
                for (int j = 0; j < 4; j++) {
                    wmma::mma_sync(acc[i][j], al[i], bh[j], acc[i][j]);
                    wmma::mma_sync(acc[i][j], ah[i], bl[j], acc[i][j]);
                    wmma::mma_sync(acc[i][j], ah[i], bh[j], acc[i][j]);
                }
        }
    }

#pragma unroll
    for (int i = 0; i < 2; i++)
#pragma unroll
        for (int j = 0; j < 4; j++)
            wmma::store_matrix_sync(
                C + (size_t)(mBase + wm * 32 + i * 16) * N + nBase + wn * 64 + j * 16,
                acc[i][j], N, wmma::mem_row_major);
}

// ---------------------------------------------------------------------------
// RoPE (in place)
// ---------------------------------------------------------------------------
__global__ void rope_kernel(float* __restrict__ X,
                            const float* __restrict__ cosb,
                            const float* __restrict__ sinb, int nHeads)
{
    int idx = blockIdx.x * blockDim.x + threadIdx.x;
    int total = S_LEN * nHeads * (H_DIM / 2);
    if (idx >= total) return;
    int d = idx & 63;
    int t = idx >> 6;
    int hh = t % nHeads;
    int s  = t / nHeads;
    float c1 = cosb[s * H_DIM + d];
    float s1 = sinb[s * H_DIM + d];
    float c2 = cosb[s * H_DIM + d + 64];
    float s2 = sinb[s * H_DIM + d + 64];
    size_t base = (size_t)s * nHeads * H_DIM + (size_t)hh * H_DIM + d;
    float x1 = X[base];
    float x2 = X[base + 64];
    X[base]      = x1 * c1 - x2 * s1;
    X[base + 64] = x2 * c2 + x1 * s2;
}

// ---------------------------------------------------------------------------
// Scores (3xTF32): attn[h][m][n] = SCALING * dot(q[m,h,:], k[n,h/4,:])
// ---------------------------------------------------------------------------
__global__ void __launch_bounds__(256) scores_kernel(float* __restrict__ attn)
{
    const int h = blockIdx.z;
    const int mBase = blockIdx.y * 128;
    const int nBase = blockIdx.x * 128;
    if (nBase > mBase + 127) return;

    __shared__ float As[128][20];
    __shared__ float Bs[128][20];

    const int tid = threadIdx.x;
    const int warp = tid >> 5;
    const int wm = warp & 3;
    const int wn = warp >> 2;
    const int lr = tid >> 1;
    const int lc = (tid & 1) * 8;

    wmma::fragment<wmma::accumulator, 16, 16, 8, float> acc[2][4];
#pragma unroll
    for (int i = 0; i < 2; i++)
#pragma unroll
        for (int j = 0; j < 4; j++) wmma::fill_fragment(acc[i][j], 0.0f);

    const float* Ap = g_q + (size_t)(mBase + lr) * (N_H * H_DIM) + h * H_DIM + lc;
    const float* Bp = g_k + (size_t)(nBase + lr) * (N_KV * H_DIM) + (h >> 2) * H_DIM + lc;

#pragma unroll 1
    for (int k0 = 0; k0 < H_DIM; k0 += 16) {
        float4 a0 = *(const float4*)(Ap + k0);
        float4 a1 = *(const float4*)(Ap + k0 + 4);
        float4 b0 = *(const float4*)(Bp + k0);
        float4 b1 = *(const float4*)(Bp + k0 + 4);
        __syncthreads();
        *(float4*)&As[lr][lc]     = a0; *(float4*)&As[lr][lc + 4] = a1;
        *(float4*)&Bs[lr][lc]     = b0; *(float4*)&Bs[lr][lc + 4] = b1;
        __syncthreads();
#pragma unroll
        for (int ks = 0; ks < 16; ks += 8) {
            wmma::fragment<wmma::matrix_a, 16, 16, 8, wmma::precision::tf32, wmma::row_major> ah[2], al[2];
            wmma::fragment<wmma::matrix_b, 16, 16, 8, wmma::precision::tf32, wmma::col_major> bh[4], bl[4];
#pragma unroll
            for (int i = 0; i < 2; i++) {
                wmma::fragment<wmma::matrix_a, 16, 16, 8, wmma::precision::tf32, wmma::row_major> raw;
                wmma::load_matrix_sync(raw, &As[wm * 32 + i * 16][ks], 20);
                split_frag(raw, ah[i], al[i]);
            }
#pragma unroll
            for (int j = 0; j < 4; j++) {
                wmma::fragment<wmma::matrix_b, 16, 16, 8, wmma::precision::tf32, wmma::col_major> raw;
                wmma::load_matrix_sync(raw, &Bs[wn * 64 + j * 16][ks], 20);
                split_frag(raw, bh[j], bl[j]);
            }
#pragma unroll
            for (int i = 0; i < 2; i++)
#pragma unroll
                for (int j = 0; j < 4; j++) {
                    wmma::mma_sync(acc[i][j], al[i], bh[j], acc[i][j]);
                    wmma::mma_sync(acc[i][j], ah[i], bl[j], acc[i][j]);
                    wmma::mma_sync(acc[i][j], ah[i], bh[j], acc[i][j]);
                }
        }
    }

    float* base = attn + (size_t)h * S_LEN * S_LEN;
#pragma unroll
    for (int i = 0; i < 2; i++)
#pragma unroll
        for (int j = 0; j < 4; j++) {
#pragma unroll
            for (int t = 0; t < acc[i][j].num_elements; t++) acc[i][j].x[t] *= SCALING;
            wmma::store_matrix_sync(
                base + (size_t)(mBase + wm * 32 + i * 16) * S_LEN + nBase + wn * 64 + j * 16,
                acc[i][j], S_LEN, wmma::mem_row_major);
        }
}

// ---------------------------------------------------------------------------
// Block reductions (256 threads)
// ---------------------------------------------------------------------------
__device__ __forceinline__ float block_reduce_sum(float v, float* sm)
{
#pragma unroll
    for (int o = 16; o > 0; o >>= 1) v += __shfl_down_sync(0xffffffffu, v, o);
    const int lane = threadIdx.x & 31, wid = threadIdx.x >> 5;
    __syncthreads();
    if (lane == 0) sm[wid] = v;
    __syncthreads();
    if (wid == 0) {
        v = (lane < 8) ? sm[lane] : 0.f;
#pragma unroll
        for (int o = 4; o > 0; o >>= 1) v += __shfl_down_sync(0xffffffffu, v, o);
        if (lane == 0) sm[8] = v;
    }
    __syncthreads();
    return sm[8];
}

__device__ __forceinline__ float block_reduce_max(float v, float* sm)
{
#pragma unroll
    for (int o = 16; o > 0; o >>= 1) v = fmaxf(v, __shfl_down_sync(0xffffffffu, v, o));
    const int lane = threadIdx.x & 31, wid = threadIdx.x >> 5;
    __syncthreads();
    if (lane == 0) sm[wid] = v;
    __syncthreads();
    if (wid == 0) {
        v = (lane < 8) ? sm[lane] : -INFINITY;
#pragma unroll
        for (int o = 4; o > 0; o >>= 1) v = fmaxf(v, __shfl_down_sync(0xffffffffu, v, o));
        if (lane == 0) sm[8] = v;
    }
    __syncthreads();
    return sm[8];
}

// ---------------------------------------------------------------------------
// alpha-entmax (alpha=1.5), 50-iter bisection. One block per (head, row).
// ---------------------------------------------------------------------------
__global__ void __launch_bounds__(256) entmax_kernel(float* __restrict__ attn)
{
    __shared__ float sm[9];
    const int row = blockIdx.x;
    const int h = row >> 11;
    const int q = row & 2047;
    float* x = attn + (size_t)h * S_LEN * S_LEN + (size_t)q * S_LEN;
    const int n = q + 1;
    const int tid = threadIdx.x;

    float X[8];
    float lmax = -INFINITY;
#pragma unroll
    for (int i = 0; i < 8; i++) {
        int j = tid + i * 256;
        if (j < n) {
            float v = x[j] * 0.5f;
            X[i] = v;
            lmax = fmaxf(lmax, v);
        } else {
            X[i] = -INFINITY;
        }
    }
    float maxv = block_reduce_max(lmax, sm);

    float tau_lo = maxv - 1.0f;
    float dm = DM0;
    float tau_m = tau_lo;
#pragma unroll 1
    for (int it = 0; it < 50; it++) {
        dm *= 0.5f;
        tau_m = tau_lo + dm;
        float ls = 0.f;
#pragma unroll
        for (int i = 0; i < 8; i++) {
            float t = fmaxf(X[i] - tau_m, 0.f);
            ls = fmaf(t, t, ls);
        }
        float f = block_reduce_sum(ls, sm);
        if (f >= 1.0f) tau_lo = tau_m;
    }

    float p[8];
    float ls = 0.f;
#pragma unroll
    for (int i = 0; i < 8; i++) {
        float t = fmaxf(X[i] - tau_m, 0.f);
        p[i] = t * t;
        ls += p[i];
    }
    float s = block_reduce_sum(ls, sm);
    float inv = 1.0f / s;
#pragma unroll
    for (int i = 0; i < 8; i++) {
        int j = tid + i * 256;
        x[j] = (j < n) ? p[i] * inv : 0.0f;
    }
}

// ---------------------------------------------------------------------------
// attn @ V (3xTF32): ctx[m, h*128+n] = sum_k attn[h][m][k] * v[k, (h/4)*128+n]
// ---------------------------------------------------------------------------
__global__ void __launch_bounds__(256) av_kernel(const float* __restrict__ attn)
{
    const int h = blockIdx.z;
    const int mBase = blockIdx.y * 128;

    __shared__ float As[128][20];
    __shared__ float Bs[16][132];

    const int tid = threadIdx.x;
    const int warp = tid >> 5;
    const int wm = warp & 3;
    const int wn = warp >> 2;

    const int lrA = tid >> 1;
    const int lcA = (tid & 1) * 8;
    const int krB = tid >> 4;
    const int ncB = (tid & 15) * 8;

    const float* A = attn + (size_t)h * S_LEN * S_LEN;
    const float* B = g_v + (h >> 2) * H_DIM;

    wmma::fragment<wmma::accumulator, 16, 16, 8, float> acc[2][4];
#pragma unroll
    for (int i = 0; i < 2; i++)
#pragma unroll
        for (int j = 0; j < 4; j++) wmma::fill_fragment(acc[i][j], 0.0f);

    const int kmax = mBase + 128;
    for (int k0 = 0; k0 < kmax; k0 += 16) {
        float4 a0 = *(const float4*)(A + (size_t)(mBase + lrA) * S_LEN + k0 + lcA);
        float4 a1 = *(const float4*)(A + (size_t)(mBase + lrA) * S_LEN + k0 + lcA + 4);
        float4 b0 = *(const float4*)(B + (size_t)(k0 + krB) * (N_KV * H_DIM) + ncB);
        float4 b1 = *(const float4*)(B + (size_t)(k0 + krB) * (N_KV * H_DIM) + ncB + 4);
        __syncthreads();
        *(float4*)&As[lrA][lcA]     = a0; *(float4*)&As[lrA][lcA + 4] = a1;
        *(float4*)&Bs[krB][ncB]     = b0; *(float4*)&Bs[krB][ncB + 4] = b1;
        __syncthreads();
#pragma unroll
        for (int ks = 0; ks < 16; ks += 8) {
            wmma::fragment<wmma::matrix_a, 16, 16, 8, wmma::precision::tf32, wmma::row_major> ah[2], al[2];
            wmma::fragment<wmma::matrix_b, 16, 16, 8, wmma::precision::tf32, wmma::row_major> bh[4], bl[4];
#pragma unroll
            for (int i = 0; i < 2; i++) {
                wmma::fragment<wmma::matrix_a, 16, 16, 8, wmma::precision::tf32, wmma::row_major> raw;
                wmma::load_matrix_sync(raw, &As[wm * 32 + i * 16][ks], 20);
                split_frag(raw, ah[i], al[i]);
            }
#pragma unroll
            for (int j = 0; j < 4; j++) {
                wmma::fragment<wmma::matrix_b, 16, 16, 8, wmma::precision::tf32, wmma::row_major> raw;
                wmma::load_matrix_sync(raw, &Bs[ks][wn * 64 + j * 16], 132);
                split_frag(raw, bh[j], bl[j]);
            }
#pragma unroll
            for (int i = 0; i < 2; i++)
#pragma unroll
                for (int j = 0; j < 4; j++) {
                    wmma::mma_sync(acc[i][j], al[i], bh[j], acc[i][j]);
                    wmma::mma_sync(acc[i][j], ah[i], bl[j], acc[i][j]);
                    wmma::mma_sync(acc[i][j], ah[i], bh[j], acc[i][j]);
                }
        }
    }

#pragma unroll
    for (int i = 0; i < 2; i++)
#pragma unroll
        for (int j = 0; j < 4; j++)
            wmma::store_matrix_sync(
                g_ctx + (size_t)(mBase + wm * 32 + i * 16) * (N_H * H_DIM)
                      + h * H_DIM + wn * 64 + j * 16,
                acc[i][j], N_H * H_DIM, wmma::mem_row_major);
}

// ---------------------------------------------------------------------------
extern "C" void kernel_launch(void* const* d_in, const int* in_sizes, int n_in,
                              void* d_out, int out_size)
{
    const float* hs   = (const float*)d_in[0];
    const float* cosb = (const float*)d_in[1];
    const float* sinb = (const float*)d_in[2];
    const float* wq   = (const float*)d_in[3];
    const float* wk   = (const float*)d_in[4];
    const float* wv   = (const float*)d_in[5];
    const float* wo   = (const float*)d_in[6];
    float* out = (float*)d_out;

    float *qp, *kp, *vp, *cp, *ap;
    cudaGetSymbolAddress((void**)&qp, g_q);
    cudaGetSymbolAddress((void**)&kp, g_k);
    cudaGetSymbolAddress((void**)&vp, g_v);
    cudaGetSymbolAddress((void**)&cp, g_ctx);
    cudaGetSymbolAddress((void**)&ap, g_attn);

    const size_t need = (size_t)S_LEN * D_MODEL + (size_t)N_H * S_LEN * S_LEN;
    float* attnBuf = ((size_t)out_size >= need) ? (out + (size_t)S_LEN * D_MODEL) : ap;

    // 1) projections (3xTF32 tensor cores)
    wgemm_nt<<<dim3(D_MODEL / 128, S_LEN / 128), 256>>>(hs, wq, qp, S_LEN, D_MODEL, D_MODEL);
    wgemm_nt<<<dim3((N_KV * H_DIM) / 128, S_LEN / 128), 256>>>(hs, wk, kp, S_LEN, N_KV * H_DIM, D_MODEL);
    wgemm_nt<<<dim3((N_KV * H_DIM) / 128, S_LEN / 128), 256>>>(hs, wv, vp, S_LEN, N_KV * H_DIM, D_MODEL);

    // 2) RoPE
    {
        int totQ = S_LEN * N_H * (H_DIM / 2);
        int totK = S_LEN * N_KV * (H_DIM / 2);
        rope_kernel<<<(totQ + 255) / 256, 256>>>(qp, cosb, sinb, N_H);
        rope_kernel<<<(totK + 255) / 256, 256>>>(kp, cosb, sinb, N_KV);
    }

    // 3) causal scores
    scores_kernel<<<dim3(S_LEN / 128, S_LEN / 128, N_H), 256>>>(attnBuf);

    // 4) entmax in place
    entmax_kernel<<<N_H * S_LEN, 256>>>(attnBuf);

    // 5) attn @ v -> ctx
    av_kernel<<<dim3(1, S_LEN / 128, N_H), 256>>>(attnBuf);

    // 6) out = ctx @ wo^T
    wgemm_nt<<<dim3(D_MODEL / 128, S_LEN / 128), 256>>>(cp, wo, out, S_LEN, D_MODEL, D_MODEL);
}

// round 5
// speedup vs baseline: 1.6521x; 1.6521x over previous
#include <cuda_runtime.h>
#include <cuda_bf16.h>
#include <mma.h>
#include <math.h>
#include <stdint.h>

using namespace nvcuda;

#define S_LEN 2048
#define D_MODEL 2048
#define N_H 16
#define N_KV 4
#define H_DIM 128
#define SCALING 0.08838834764831845f
#define DM0 0.9779029130879204f

// Scratch (allocation-free rule: __device__ globals)
__device__ float g_q[(size_t)S_LEN * N_H * H_DIM];
__device__ float g_k[(size_t)S_LEN * N_KV * H_DIM];
__device__ float g_v[(size_t)S_LEN * N_KV * H_DIM];
__device__ float g_ctx[(size_t)S_LEN * N_H * H_DIM];
__device__ float g_attn[(size_t)N_H * S_LEN * S_LEN];

typedef __nv_bfloat16 bf16;

__device__ __forceinline__ void split_bf16(float v, bf16& hi, bf16& lo) {
    hi = __float2bfloat16_rn(v);
    lo = __float2bfloat16_rn(v - __bfloat162float(hi));
}

// ===========================================================================
// Split-bf16 WMMA NT GEMM: C[M,N] = A[M,K] * B[N,K]^T (row-major A,B), fp32 acc.
// BM=BN=128, BK=32, 256 threads (8 warps; warp tile 32m x 64n).
// hi/lo split computed once per element during SMEM fill.
// ===========================================================================
__global__ void __launch_bounds__(256) wgemm_nt(
    const float* __restrict__ A, const float* __restrict__ B,
    float* __restrict__ C, int M, int N, int K)
{
    __shared__ bf16 Ah[128][40], Al[128][40];
    __shared__ bf16 Bh[128][40], Bl[128][40];

    const int tid = threadIdx.x;
    const int warp = tid >> 5;
    const int wm = warp & 3;       // 4 m-groups * 32 rows
    const int wn = warp >> 2;      // 2 n-groups * 64 cols
    const int mBase = blockIdx.y * 128;
    const int nBase = blockIdx.x * 128;

    const int lr = tid >> 1;            // 0..127
    const int lc = (tid & 1) * 16;      // 0 or 16

    wmma::fragment<wmma::accumulator, 16, 16, 16, float> acc[2][4];
#pragma unroll
    for (int i = 0; i < 2; i++)
#pragma unroll
        for (int j = 0; j < 4; j++) wmma::fill_fragment(acc[i][j], 0.0f);

    const float* Ap = A + (size_t)(mBase + lr) * K + lc;
    const float* Bp = B + (size_t)(nBase + lr) * K + lc;

    for (int k0 = 0; k0 < K; k0 += 32) {
        float4 va[4], vb[4];
#pragma unroll
        for (int t = 0; t < 4; t++) {
            va[t] = *(const float4*)(Ap + k0 + t * 4);
            vb[t] = *(const float4*)(Bp + k0 + t * 4);
        }
        __syncthreads();
#pragma unroll
        for (int t = 0; t < 4; t++) {
            const float* pa = (const float*)&va[t];
            const float* pb = (const float*)&vb[t];
#pragma unroll
            for (int e = 0; e < 4; e++) {
                bf16 h, l;
                split_bf16(pa[e], h, l);
                Ah[lr][lc + t * 4 + e] = h; Al[lr][lc + t * 4 + e] = l;
                split_bf16(pb[e], h, l);
                Bh[lr][lc + t * 4 + e] = h; Bl[lr][lc + t * 4 + e] = l;
            }
        }
        __syncthreads();
#pragma unroll
        for (int ks = 0; ks < 32; ks += 16) {
            wmma::fragment<wmma::matrix_a, 16, 16, 16, bf16, wmma::row_major> ah[2], al[2];
            wmma::fragment<wmma::matrix_b, 16, 16, 16, bf16, wmma::col_major> bh[4], bl[4];
#pragma unroll
            for (int i = 0; i < 2; i++) {
                wmma::load_matrix_sync(ah[i], &Ah[wm * 32 + i * 16][ks], 40);
                wmma::load_matrix_sync(al[i], &Al[wm * 32 + i * 16][ks], 40);
            }
#pragma unroll
            for (int j = 0; j < 4; j++) {
                wmma::load_matrix_sync(bh[j], &Bh[wn * 64 + j * 16][ks], 40);
                wmma::load_matrix_sync(bl[j], &Bl[wn * 64 + j * 16][ks], 40);
            }
#pragma unroll
            for (int i = 0; i < 2; i++)
#pragma unroll
                for (int j = 0; j < 4; j++) {
                    wmma::mma_sync(acc[i][j], ah[i], bl[j], acc[i][j]);
                    wmma::mma_sync(acc[i][j], al[i], bh[j], acc[i][j]);
                    wmma::mma_sync(acc[i][j], ah[i], bh[j], acc[i][j]);
                }
        }
    }

#pragma unroll
    for (int i = 0; i < 2; i++)
#pragma unroll
        for (int j = 0; j < 4; j++)
            wmma::store_matrix_sync(
                C + (size_t)(mBase + wm * 32 + i * 16) * N + nBase + wn * 64 + j * 16,
                acc[i][j], N, wmma::mem_row_major);
}

// ===========================================================================
// RoPE (in place)
// ===========================================================================
__global__ void rope_kernel(float* __restrict__ X,
                            const float* __restrict__ cosb,
                            const float* __restrict__ sinb, int nHeads)
{
    int idx = blockIdx.x * blockDim.x + threadIdx.x;
    int total = S_LEN * nHeads * (H_DIM / 2);
    if (idx >= total) return;
    int d = idx & 63;
    int t = idx >> 6;
    int hh = t % nHeads;
    int s  = t / nHeads;
    float c1 = cosb[s * H_DIM + d];
    float s1 = sinb[s * H_DIM + d];
    float c2 = cosb[s * H_DIM + d + 64];
    float s2 = sinb[s * H_DIM + d + 64];
    size_t base = (size_t)s * nHeads * H_DIM + (size_t)hh * H_DIM + d;
    float x1 = X[base];
    float x2 = X[base + 64];
    X[base]      = x1 * c1 - x2 * s1;
    X[base + 64] = x2 * c2 + x1 * s2;
}

// ===========================================================================
// Scores (split-bf16 WMMA): attn[h][m][n] = SCALING * dot(q[m,h,:], k[n,h/4,:])
// Skips tiles fully above the diagonal.
// ===========================================================================
__global__ void __launch_bounds__(256) scores_kernel(float* __restrict__ attn)
{
    const int h = blockIdx.z;
    const int mBase = blockIdx.y * 128;
    const int nBase = blockIdx.x * 128;
    if (nBase > mBase + 127) return;

    __shared__ bf16 Ah[128][40], Al[128][40];
    __shared__ bf16 Bh[128][40], Bl[128][40];

    const int tid = threadIdx.x;
    const int warp = tid >> 5;
    const int wm = warp & 3;
    const int wn = warp >> 2;
    const int lr = tid >> 1;
    const int lc = (tid & 1) * 16;

    wmma::fragment<wmma::accumulator, 16, 16, 16, float> acc[2][4];
#pragma unroll
    for (int i = 0; i < 2; i++)
#pragma unroll
        for (int j = 0; j < 4; j++) wmma::fill_fragment(acc[i][j], 0.0f);

    const float* Ap = g_q + (size_t)(mBase + lr) * (N_H * H_DIM) + h * H_DIM + lc;
    const float* Bp = g_k + (size_t)(nBase + lr) * (N_KV * H_DIM) + (h >> 2) * H_DIM + lc;

#pragma unroll 1
    for (int k0 = 0; k0 < H_DIM; k0 += 32) {
        float4 va[4], vb[4];
#pragma unroll
        for (int t = 0; t < 4; t++) {
            va[t] = *(const float4*)(Ap + k0 + t * 4);
            vb[t] = *(const float4*)(Bp + k0 + t * 4);
        }
        __syncthreads();
#pragma unroll
        for (int t = 0; t < 4; t++) {
            const float* pa = (const float*)&va[t];
            const float* pb = (const float*)&vb[t];
#pragma unroll
            for (int e = 0; e < 4; e++) {
                bf16 hh2, ll;
                split_bf16(pa[e], hh2, ll);
                Ah[lr][lc + t * 4 + e] = hh2; Al[lr][lc + t * 4 + e] = ll;
                split_bf16(pb[e], hh2, ll);
                Bh[lr][lc + t * 4 + e] = hh2; Bl[lr][lc + t * 4 + e] = ll;
            }
        }
        __syncthreads();
#pragma unroll
        for (int ks = 0; ks < 32; ks += 16) {
            wmma::fragment<wmma::matrix_a, 16, 16, 16, bf16, wmma::row_major> ah[2], al[2];
            wmma::fragment<wmma::matrix_b, 16, 16, 16, bf16, wmma::col_major> bh[4], bl[4];
#pragma unroll
            for (int i = 0; i < 2; i++) {
                wmma::load_matrix_sync(ah[i], &Ah[wm * 32 + i * 16][ks], 40);
                wmma::load_matrix_sync(al[i], &Al[wm * 32 + i * 16][ks], 40);
            }
#pragma unroll
            for (int j = 0; j < 4; j++) {
                wmma::load_matrix_sync(bh[j], &Bh[wn * 64 + j * 16][ks], 40);
                wmma::load_matrix_sync(bl[j], &Bl[wn * 64 + j * 16][ks], 40);
            }
#pragma unroll
            for (int i = 0; i < 2; i++)
#pragma unroll
                for (int j = 0; j < 4; j++) {
                    wmma::mma_sync(acc[i][j], ah[i], bl[j], acc[i][j]);
                    wmma::mma_sync(acc[i][j], al[i], bh[j], acc[i][j]);
                    wmma::mma_sync(acc[i][j], ah[i], bh[j], acc[i][j]);
                }
        }
    }

    float* base = attn + (size_t)h * S_LEN * S_LEN;
#pragma unroll
    for (int i = 0; i < 2; i++)
#pragma unroll
        for (int j = 0; j < 4; j++) {
#pragma unroll
            for (int t = 0; t < acc[i][j].num_elements; t++) acc[i][j].x[t] *= SCALING;
            wmma::store_matrix_sync(
                base + (size_t)(mBase + wm * 32 + i * 16) * S_LEN + nBase + wn * 64 + j * 16,
                acc[i][j], S_LEN, wmma::mem_row_major);
        }
}

// ===========================================================================
// Block reductions (256 threads)
// ===========================================================================
__device__ __forceinline__ float block_reduce_sum(float v, float* sm)
{
#pragma unroll
    for (int o = 16; o > 0; o >>= 1) v += __shfl_down_sync(0xffffffffu, v, o);
    const int lane = threadIdx.x & 31, wid = threadIdx.x >> 5;
    __syncthreads();
    if (lane == 0) sm[wid] = v;
    __syncthreads();
    if (wid == 0) {
        v = (lane < 8) ? sm[lane] : 0.f;
#pragma unroll
        for (int o = 4; o > 0; o >>= 1) v += __shfl_down_sync(0xffffffffu, v, o);
        if (lane == 0) sm[8] = v;
    }
    __syncthreads();
    return sm[8];
}

__device__ __forceinline__ float block_reduce_max(float v, float* sm)
{
#pragma unroll
    for (int o = 16; o > 0; o >>= 1) v = fmaxf(v, __shfl_down_sync(0xffffffffu, v, o));
    const int lane = threadIdx.x & 31, wid = threadIdx.x >> 5;
    __syncthreads();
    if (lane == 0) sm[wid] = v;
    __syncthreads();
    if (wid == 0) {
        v = (lane < 8) ? sm[lane] : -INFINITY;
#pragma unroll
        for (int o = 4; o > 0; o >>= 1) v = fmaxf(v, __shfl_down_sync(0xffffffffu, v, o));
        if (lane == 0) sm[8] = v;
    }
    __syncthreads();
    return sm[8];
}

// ===========================================================================
// alpha-entmax (alpha=1.5), 50-iter bisection. One block per (head, row).
// ===========================================================================
__global__ void __launch_bounds__(256) entmax_kernel(float* __restrict__ attn)
{
    __shared__ float sm[9];
    const int row = blockIdx.x;
    const int h = row >> 11;
    const int q = row & 2047;
    float* x = attn + (size_t)h * S_LEN * S_LEN + (size_t)q * S_LEN;
    const int n = q + 1;
    const int tid = threadIdx.x;

    float X[8];
    float lmax = -INFINITY;
#pragma unroll
    for (int i = 0; i < 8; i++) {
        int j = tid + i * 256;
        if (j < n) {
            float v = x[j] * 0.5f;
            X[i] = v;
            lmax = fmaxf(lmax, v);
        } else {
            X[i] = -INFINITY;
        }
    }
    float maxv = block_reduce_max(lmax, sm);

    float tau_lo = maxv - 1.0f;
    float dm = DM0;
    float tau_m = tau_lo;
#pragma unroll 1
    for (int it = 0; it < 50; it++) {
        dm *= 0.5f;
        tau_m = tau_lo + dm;
        float ls = 0.f;
#pragma unroll
        for (int i = 0; i < 8; i++) {
            float t = fmaxf(X[i] - tau_m, 0.f);
            ls = fmaf(t, t, ls);
        }
        float f = block_reduce_sum(ls, sm);
        if (f >= 1.0f) tau_lo = tau_m;
    }

    float p[8];
    float ls = 0.f;
#pragma unroll
    for (int i = 0; i < 8; i++) {
        float t = fmaxf(X[i] - tau_m, 0.f);
        p[i] = t * t;
        ls += p[i];
    }
    float s = block_reduce_sum(ls, sm);
    float inv = 1.0f / s;
#pragma unroll
    for (int i = 0; i < 8; i++) {
        int j = tid + i * 256;
        x[j] = (j < n) ? p[i] * inv : 0.0f;
    }
}

// ===========================================================================
// attn @ V (split-bf16 WMMA): ctx[m,h*128+n] = sum_k attn[h][m][k]*v[k,(h/4)*128+n]
// A row-major [M][K] (causal K range), B row-major [K][N]. BK=32.
// ===========================================================================
__global__ void __launch_bounds__(256) av_kernel(const float* __restrict__ attn)
{
    const int h = blockIdx.z;
    const int mBase = blockIdx.y * 128;

    __shared__ bf16 Ah[128][40], Al[128][40];
    __shared__ bf16 Bh[32][136], Bl[32][136];

    const int tid = threadIdx.x;
    const int warp = tid >> 5;
    const int wm = warp & 3;
    const int wn = warp >> 2;

    const int lrA = tid >> 1;
    const int lcA = (tid & 1) * 16;
    const int krB = tid >> 3;          // 0..31
    const int ncB = (tid & 7) * 16;    // 0..112

    const float* A = attn + (size_t)h * S_LEN * S_LEN;
    const float* B = g_v + (h >> 2) * H_DIM;

    wmma::fragment<wmma::accumulator, 16, 16, 16, float> acc[2][4];
#pragma unroll
    for (int i = 0; i < 2; i++)
#pragma unroll
        for (int j = 0; j < 4; j++) wmma::fill_fragment(acc[i][j], 0.0f);

    const int kmax = mBase + 128;
    for (int k0 = 0; k0 < kmax; k0 += 32) {
        float4 va[4], vb[4];
#pragma unroll
        for (int t = 0; t < 4; t++) {
            va[t] = *(const float4*)(A + (size_t)(mBase + lrA) * S_LEN + k0 + lcA + t * 4);
            vb[t] = *(const float4*)(B + (size_t)(k0 + krB) * (N_KV * H_DIM) + ncB + t * 4);
        }
        __syncthreads();
#pragma unroll
        for (int t = 0; t < 4; t++) {
            const float* pa = (const float*)&va[t];
            const float* pb = (const float*)&vb[t];
#pragma unroll
            for (int e = 0; e < 4; e++) {
                bf16 hh2, ll;
                split_bf16(pa[e], hh2, ll);
                Ah[lrA][lcA + t * 4 + e] = hh2; Al[lrA][lcA + t * 4 + e] = ll;
                split_bf16(pb[e], hh2, ll);
                Bh[krB][ncB + t * 4 + e] = hh2; Bl[krB][ncB + t * 4 + e] = ll;
            }
        }
        __syncthreads();
#pragma unroll
        for (int ks = 0; ks < 32; ks += 16) {
            wmma::fragment<wmma::matrix_a, 16, 16, 16, bf16, wmma::row_major> ah[2], al[2];
            wmma::fragment<wmma::matrix_b, 16, 16, 16, bf16, wmma::row_major> bh[4], bl[4];
#pragma unroll
            for (int i = 0; i < 2; i++) {
                wmma::load_matrix_sync(ah[i], &Ah[wm * 32 + i * 16][ks], 40);
                wmma::load_matrix_sync(al[i], &Al[wm * 32 + i * 16][ks], 40);
            }
#pragma unroll
            for (int j = 0; j < 4; j++) {
                wmma::load_matrix_sync(bh[j], &Bh[ks][wn * 64 + j * 16], 136);
                wmma::load_matrix_sync(bl[j], &Bl[ks][wn * 64 + j * 16], 136);
            }
#pragma unroll
            for (int i = 0; i < 2; i++)
#pragma unroll
                for (int j = 0; j < 4; j++) {
                    wmma::mma_sync(acc[i][j], ah[i], bl[j], acc[i][j]);
                    wmma::mma_sync(acc[i][j], al[i], bh[j], acc[i][j]);
                    wmma::mma_sync(acc[i][j], ah[i], bh[j], acc[i][j]);
                }
        }
    }

#pragma unroll
    for (int i = 0; i < 2; i++)
#pragma unroll
        for (int j = 0; j < 4; j++)
            wmma::store_matrix_sync(
                g_ctx + (size_t)(mBase + wm * 32 + i * 16) * (N_H * H_DIM)
                      + h * H_DIM + wn * 64 + j * 16,
                acc[i][j], N_H * H_DIM, wmma::mem_row_major);
}

// ===========================================================================
extern "C" void kernel_launch(void* const* d_in, const int* in_sizes, int n_in,
                              void* d_out, int out_size)
{
    const float* hs   = (const float*)d_in[0];
    const float* cosb = (const float*)d_in[1];
    const float* sinb = (const float*)d_in[2];
    const float* wq   = (const float*)d_in[3];
    const float* wk   = (const float*)d_in[4];
    const float* wv   = (const float*)d_in[5];
    const float* wo   = (const float*)d_in[6];
    float* out = (float*)d_out;

    float *qp, *kp, *vp, *cp, *ap;
    cudaGetSymbolAddress((void**)&qp, g_q);
    cudaGetSymbolAddress((void**)&kp, g_k);
    cudaGetSymbolAddress((void**)&vp, g_v);
    cudaGetSymbolAddress((void**)&cp, g_ctx);
    cudaGetSymbolAddress((void**)&ap, g_attn);

    const size_t need = (size_t)S_LEN * D_MODEL + (size_t)N_H * S_LEN * S_LEN;
    float* attnBuf = ((size_t)out_size >= need) ? (out + (size_t)S_LEN * D_MODEL) : ap;

    // 1) projections (split-bf16 tensor cores)
    wgemm_nt<<<dim3(D_MODEL / 128, S_LEN / 128), 256>>>(hs, wq, qp, S_LEN, D_MODEL, D_MODEL);
    wgemm_nt<<<dim3((N_KV * H_DIM) / 128, S_LEN / 128), 256>>>(hs, wk, kp, S_LEN, N_KV * H_DIM, D_MODEL);
    wgemm_nt<<<dim3((N_KV * H_DIM) / 128, S_LEN / 128), 256>>>(hs, wv, vp, S_LEN, N_KV * H_DIM, D_MODEL);

    // 2) RoPE
    {
        int totQ = S_LEN * N_H * (H_DIM / 2);
        int totK = S_LEN * N_KV * (H_DIM / 2);
        rope_kernel<<<(totQ + 255) / 256, 256>>>(qp, cosb, sinb, N_H);
        rope_kernel<<<(totK + 255) / 256, 256>>>(kp, cosb, sinb, N_KV);
    }

    // 3) causal scores
    scores_kernel<<<dim3(S_LEN / 128, S_LEN / 128, N_H), 256>>>(attnBuf);

    // 4) entmax in place
    entmax_kernel<<<N_H * S_LEN, 256>>>(attnBuf);

    // 5) attn @ v -> ctx
    av_kernel<<<dim3(1, S_LEN / 128, N_H), 256>>>(attnBuf);

    // 6) out = ctx @ wo^T
    wgemm_nt<<<dim3(D_MODEL / 128, S_LEN / 128), 256>>>(cp, wo, out, S_LEN, D_MODEL, D_MODEL);
}

// round 6
// speedup vs baseline: 2.3154x; 1.4014x over previous
#include <cuda_runtime.h>
#include <cuda_bf16.h>
#include <mma.h>
#include <math.h>
#include <stdint.h>

using namespace nvcuda;

#define S_LEN 2048
#define D_MODEL 2048
#define N_H 16
#define N_KV 4
#define H_DIM 128
#define SCALING 0.08838834764831845f
#define DM0 0.9779029130879204f
#define KV_DIM (N_KV * H_DIM)

typedef __nv_bfloat16 bf16;

// fp32 scratch
__device__ float g_q[(size_t)S_LEN * N_H * H_DIM];
__device__ float g_k[(size_t)S_LEN * KV_DIM];
__device__ float g_v[(size_t)S_LEN * KV_DIM];
__device__ float g_ctx[(size_t)S_LEN * N_H * H_DIM];
__device__ float g_attn[(size_t)N_H * S_LEN * S_LEN];

// pre-split bf16 hi/lo scratch
#define SZ_BIG  ((size_t)2048 * 2048)
#define SZ_SML  ((size_t)2048 * 512)
__device__ bf16 g_hsh[SZ_BIG], g_hsl[SZ_BIG];
__device__ bf16 g_wqh[SZ_BIG], g_wql[SZ_BIG];
__device__ bf16 g_wkh[SZ_SML], g_wkl[SZ_SML];
__device__ bf16 g_wvh[SZ_SML], g_wvl[SZ_SML];
__device__ bf16 g_woh[SZ_BIG], g_wol[SZ_BIG];
__device__ bf16 g_qh[SZ_BIG],  g_ql[SZ_BIG];
__device__ bf16 g_kh[SZ_SML],  g_kl[SZ_SML];
__device__ bf16 g_vh[SZ_SML],  g_vl[SZ_SML];
__device__ bf16 g_cth[SZ_BIG], g_ctl[SZ_BIG];

__device__ __forceinline__ void split_bf16(float v, bf16& hi, bf16& lo) {
    hi = __float2bfloat16_rn(v);
    lo = __float2bfloat16_rn(v - __bfloat162float(hi));
}
__device__ __forceinline__ uint32_t smem_u32(const void* p) {
    return (uint32_t)__cvta_generic_to_shared(p);
}
#define CP16(dst, src) asm volatile("cp.async.cg.shared.global [%0], [%1], 16;" :: "r"(dst), "l"(src))
#define CP_COMMIT()    asm volatile("cp.async.commit_group;" ::: "memory")
#define CP_WAIT1()     asm volatile("cp.async.wait_group 1;" ::: "memory")
#define CP_WAIT0()     asm volatile("cp.async.wait_group 0;" ::: "memory")

// ===========================================================================
// split: fp32 -> (bf16 hi, bf16 lo), 4 elems/thread
// ===========================================================================
__global__ void split_kernel(const float* __restrict__ x,
                             bf16* __restrict__ hi, bf16* __restrict__ lo, int n)
{
    int i = (blockIdx.x * blockDim.x + threadIdx.x) * 4;
    if (i >= n) return;
    float4 v = *(const float4*)(x + i);
    bf16 h0, l0, h1, l1, h2, l2, h3, l3;
    split_bf16(v.x, h0, l0); split_bf16(v.y, h1, l1);
    split_bf16(v.z, h2, l2); split_bf16(v.w, h3, l3);
    __nv_bfloat162* H = (__nv_bfloat162*)(hi + i);
    __nv_bfloat162* L = (__nv_bfloat162*)(lo + i);
    H[0] = __halves2bfloat162(h0, h1); H[1] = __halves2bfloat162(h2, h3);
    L[0] = __halves2bfloat162(l0, l1); L[1] = __halves2bfloat162(l2, l3);
}

// ===========================================================================
// RoPE + split: reads fp32 [S][nHeads][HD], writes rotated bf16 hi/lo
// ===========================================================================
__global__ void rope_split_kernel(const float* __restrict__ X,
                                  const float* __restrict__ cosb,
                                  const float* __restrict__ sinb, int nHeads,
                                  bf16* __restrict__ hi, bf16* __restrict__ lo)
{
    int idx = blockIdx.x * blockDim.x + threadIdx.x;
    int total = S_LEN * nHeads * (H_DIM / 2);
    if (idx >= total) return;
    int d = idx & 63;
    int t = idx >> 6;
    int hh = t % nHeads;
    int s  = t / nHeads;
    float c1 = cosb[s * H_DIM + d];
    float s1 = sinb[s * H_DIM + d];
    float c2 = cosb[s * H_DIM + d + 64];
    float s2 = sinb[s * H_DIM + d + 64];
    size_t base = (size_t)s * nHeads * H_DIM + (size_t)hh * H_DIM + d;
    float x1 = X[base];
    float x2 = X[base + 64];
    float y1 = x1 * c1 - x2 * s1;
    float y2 = x2 * c2 + x1 * s2;
    bf16 h, l;
    split_bf16(y1, h, l); hi[base] = h;      lo[base] = l;
    split_bf16(y2, h, l); hi[base + 64] = h; lo[base + 64] = l;
}

// ===========================================================================
// Pipelined split-bf16 NT GEMM core: C = A*B^T, pre-split operands.
// BM=BN=128, BK=32, 256 thr, 2-stage cp.async. SMEM tile stride 40 elems.
// Stage layout: [Ah | Al | Bh | Bl], each 128*40 = 5120 elems (10240 B).
// ===========================================================================
__device__ __forceinline__ void gemm_core(
    const bf16* __restrict__ Ah, const bf16* __restrict__ Al,
    const bf16* __restrict__ Bh, const bf16* __restrict__ Bl,
    int lda, int ldb, int K, int mBase, int nBase,
    float* __restrict__ C, int ldc, float scale)
{
    extern __shared__ bf16 sm[];
    const int tid = threadIdx.x;
    const int warp = tid >> 5;
    const int wm = warp & 3;
    const int wn = warp >> 2;

    wmma::fragment<wmma::accumulator, 16, 16, 16, float> acc[2][4];
#pragma unroll
    for (int i = 0; i < 2; i++)
#pragma unroll
        for (int j = 0; j < 4; j++) wmma::fill_fragment(acc[i][j], 0.0f);

    const int r  = tid >> 1;            // 0..127
    const int cc = (tid & 1) * 16;      // 0 or 16

    const bf16* Ap_h = Ah + (size_t)(mBase + r) * lda + cc;
    const bf16* Ap_l = Al + (size_t)(mBase + r) * lda + cc;
    const bf16* Bp_h = Bh + (size_t)(nBase + r) * ldb + cc;
    const bf16* Bp_l = Bl + (size_t)(nBase + r) * ldb + cc;
    const uint32_t dbase = smem_u32(sm + r * 40 + cc);

    const int T = K >> 5;

    // prologue
    {
        CP16(dbase,             Ap_h); CP16(dbase + 16,         Ap_h + 8);
        CP16(dbase + 10240,     Ap_l); CP16(dbase + 10240 + 16, Ap_l + 8);
        CP16(dbase + 20480,     Bp_h); CP16(dbase + 20480 + 16, Bp_h + 8);
        CP16(dbase + 30720,     Bp_l); CP16(dbase + 30720 + 16, Bp_l + 8);
        CP_COMMIT();
    }

#pragma unroll 1
    for (int t = 0; t < T; t++) {
        if (t + 1 < T) {
            const int k1 = (t + 1) * 32;
            const uint32_t d = dbase + ((t + 1) & 1) * 40960;
            CP16(d,             Ap_h + k1); CP16(d + 16,         Ap_h + k1 + 8);
            CP16(d + 10240,     Ap_l + k1); CP16(d + 10240 + 16, Ap_l + k1 + 8);
            CP16(d + 20480,     Bp_h + k1); CP16(d + 20480 + 16, Bp_h + k1 + 8);
            CP16(d + 30720,     Bp_l + k1); CP16(d + 30720 + 16, Bp_l + k1 + 8);
            CP_COMMIT();
            CP_WAIT1();
        } else {
            CP_WAIT0();
        }
        __syncthreads();

        bf16* st   = sm + (t & 1) * 20480;
        bf16* Ah_s = st;
        bf16* Al_s = st + 5120;
        bf16* Bh_s = st + 10240;
        bf16* Bl_s = st + 15360;
#pragma unroll
        for (int ks = 0; ks < 32; ks += 16) {
            wmma::fragment<wmma::matrix_a, 16, 16, 16, bf16, wmma::row_major> ah[2], al[2];
            wmma::fragment<wmma::matrix_b, 16, 16, 16, bf16, wmma::col_major> bh[4], bl[4];
#pragma unroll
            for (int i = 0; i < 2; i++) {
                wmma::load_matrix_sync(ah[i], &Ah_s[(wm * 32 + i * 16) * 40 + ks], 40);
                wmma::load_matrix_sync(al[i], &Al_s[(wm * 32 + i * 16) * 40 + ks], 40);
            }
#pragma unroll
            for (int j = 0; j < 4; j++) {
                wmma::load_matrix_sync(bh[j], &Bh_s[(wn * 64 + j * 16) * 40 + ks], 40);
                wmma::load_matrix_sync(bl[j], &Bl_s[(wn * 64 + j * 16) * 40 + ks], 40);
            }
#pragma unroll
            for (int i = 0; i < 2; i++)
#pragma unroll
                for (int j = 0; j < 4; j++) {
                    wmma::mma_sync(acc[i][j], ah[i], bl[j], acc[i][j]);
                    wmma::mma_sync(acc[i][j], al[i], bh[j], acc[i][j]);
                    wmma::mma_sync(acc[i][j], ah[i], bh[j], acc[i][j]);
                }
        }
        __syncthreads();
    }

#pragma unroll
    for (int i = 0; i < 2; i++)
#pragma unroll
        for (int j = 0; j < 4; j++) {
#pragma unroll
            for (int t = 0; t < acc[i][j].num_elements; t++) acc[i][j].x[t] *= scale;
            wmma::store_matrix_sync(
                C + (size_t)(mBase + wm * 32 + i * 16) * ldc + nBase + wn * 64 + j * 16,
                acc[i][j], ldc, wmma::mem_row_major);
        }
}

#define GEMM_SMEM (2 * 20480 * (int)sizeof(bf16))

__global__ void __launch_bounds__(256) gemm_pre_kernel(
    const bf16* Ah, const bf16* Al, const bf16* Bh, const bf16* Bl,
    float* C, int N, int K)
{
    gemm_core(Ah, Al, Bh, Bl, K, K, K, blockIdx.y * 128, blockIdx.x * 128, C, N, 1.0f);
}

__global__ void __launch_bounds__(256) scores_pre_kernel(float* __restrict__ attn)
{
    const int h = blockIdx.z;
    const int mBase = blockIdx.y * 128;
    const int nBase = blockIdx.x * 128;
    if (nBase > mBase + 127) return;
    gemm_core(g_qh + h * H_DIM, g_ql + h * H_DIM,
              g_kh + (h >> 2) * H_DIM, g_kl + (h >> 2) * H_DIM,
              N_H * H_DIM, KV_DIM, H_DIM, mBase, nBase,
              attn + (size_t)h * S_LEN * S_LEN, S_LEN, SCALING);
}

// ===========================================================================
// Block reductions (256 threads)
// ===========================================================================
__device__ __forceinline__ float block_reduce_sum(float v, float* sm)
{
#pragma unroll
    for (int o = 16; o > 0; o >>= 1) v += __shfl_down_sync(0xffffffffu, v, o);
    const int lane = threadIdx.x & 31, wid = threadIdx.x >> 5;
    __syncthreads();
    if (lane == 0) sm[wid] = v;
    __syncthreads();
    if (wid == 0) {
        v = (lane < 8) ? sm[lane] : 0.f;
#pragma unroll
        for (int o = 4; o > 0; o >>= 1) v += __shfl_down_sync(0xffffffffu, v, o);
        if (lane == 0) sm[8] = v;
    }
    __syncthreads();
    return sm[8];
}

__device__ __forceinline__ float block_reduce_max(float v, float* sm)
{
#pragma unroll
    for (int o = 16; o > 0; o >>= 1) v = fmaxf(v, __shfl_down_sync(0xffffffffu, v, o));
    const int lane = threadIdx.x & 31, wid = threadIdx.x >> 5;
    __syncthreads();
    if (lane == 0) sm[wid] = v;
    __syncthreads();
    if (wid == 0) {
        v = (lane < 8) ? sm[lane] : -INFINITY;
#pragma unroll
        for (int o = 4; o > 0; o >>= 1) v = fmaxf(v, __shfl_down_sync(0xffffffffu, v, o));
        if (lane == 0) sm[8] = v;
    }
    __syncthreads();
    return sm[8];
}

// ===========================================================================
// alpha-entmax (alpha=1.5), 32-iter bisection (fp32-converged == 50 iters).
// ===========================================================================
__global__ void __launch_bounds__(256) entmax_kernel(float* __restrict__ attn)
{
    __shared__ float sm[9];
    const int row = blockIdx.x;
    const int h = row >> 11;
    const int q = row & 2047;
    float* x = attn + (size_t)h * S_LEN * S_LEN + (size_t)q * S_LEN;
    const int n = q + 1;
    const int tid = threadIdx.x;

    float X[8];
    float lmax = -INFINITY;
#pragma unroll
    for (int i = 0; i < 8; i++) {
        int j = tid + i * 256;
        if (j < n) {
            float v = x[j] * 0.5f;
            X[i] = v;
            lmax = fmaxf(lmax, v);
        } else {
            X[i] = -INFINITY;
        }
    }
    float maxv = block_reduce_max(lmax, sm);

    float tau_lo = maxv - 1.0f;
    float dm = DM0;
    float tau_m = tau_lo;
#pragma unroll 1
    for (int it = 0; it < 32; it++) {
        dm *= 0.5f;
        tau_m = tau_lo + dm;
        float ls = 0.f;
#pragma unroll
        for (int i = 0; i < 8; i++) {
            float t = fmaxf(X[i] - tau_m, 0.f);
            ls = fmaf(t, t, ls);
        }
        float f = block_reduce_sum(ls, sm);
        if (f >= 1.0f) tau_lo = tau_m;
    }

    float p[8];
    float ls = 0.f;
#pragma unroll
    for (int i = 0; i < 8; i++) {
        float t = fmaxf(X[i] - tau_m, 0.f);
        p[i] = t * t;
        ls += p[i];
    }
    float s = block_reduce_sum(ls, sm);
    float inv = 1.0f / s;
#pragma unroll
    for (int i = 0; i < 8; i++) {
        int j = tid + i * 256;
        x[j] = (j < n) ? p[i] * inv : 0.0f;
    }
}

// ===========================================================================
// attn @ V: A fp32 (split in-kernel, read once), V pre-split. BK=32.
// ===========================================================================
__global__ void __launch_bounds__(256) av_kernel(const float* __restrict__ attn)
{
    const int h = blockIdx.z;
    const int mBase = blockIdx.y * 128;

    __shared__ bf16 Ah[128][40], Al[128][40];
    __shared__ bf16 Bh[32][136], Bl[32][136];

    const int tid = threadIdx.x;
    const int warp = tid >> 5;
    const int wm = warp & 3;
    const int wn = warp >> 2;

    const int lrA = tid >> 1;
    const int lcA = (tid & 1) * 16;
    const int krB = tid >> 3;          // 0..31
    const int ncB = (tid & 7) * 16;    // 0..112

    const float* A = attn + (size_t)h * S_LEN * S_LEN;
    const bf16* Bh_g = g_vh + (h >> 2) * H_DIM;
    const bf16* Bl_g = g_vl + (h >> 2) * H_DIM;

    wmma::fragment<wmma::accumulator, 16, 16, 16, float> acc[2][4];
#pragma unroll
    for (int i = 0; i < 2; i++)
#pragma unroll
        for (int j = 0; j < 4; j++) wmma::fill_fragment(acc[i][j], 0.0f);

    const int kmax = mBase + 128;
    for (int k0 = 0; k0 < kmax; k0 += 32) {
        float4 va[4];
#pragma unroll
        for (int t = 0; t < 4; t++)
            va[t] = *(const float4*)(A + (size_t)(mBase + lrA) * S_LEN + k0 + lcA + t * 4);
        size_t boff = (size_t)(k0 + krB) * KV_DIM + ncB;
        uint4 bh0 = *(const uint4*)(Bh_g + boff);
        uint4 bh1 = *(const uint4*)(Bh_g + boff + 8);
        uint4 bl0 = *(const uint4*)(Bl_g + boff);
        uint4 bl1 = *(const uint4*)(Bl_g + boff + 8);
        __syncthreads();
#pragma unroll
        for (int t = 0; t < 4; t++) {
            const float* pa = (const float*)&va[t];
#pragma unroll
            for (int e = 0; e < 4; e++) {
                bf16 hh2, ll;
                split_bf16(pa[e], hh2, ll);
                Ah[lrA][lcA + t * 4 + e] = hh2;
                Al[lrA][lcA + t * 4 + e] = ll;
            }
        }
        *(uint4*)&Bh[krB][ncB]     = bh0;
        *(uint4*)&Bh[krB][ncB + 8] = bh1;
        *(uint4*)&Bl[krB][ncB]     = bl0;
        *(uint4*)&Bl[krB][ncB + 8] = bl1;
        __syncthreads();
#pragma unroll
        for (int ks = 0; ks < 32; ks += 16) {
            wmma::fragment<wmma::matrix_a, 16, 16, 16, bf16, wmma::row_major> ah[2], al[2];
            wmma::fragment<wmma::matrix_b, 16, 16, 16, bf16, wmma::row_major> bh[4], bl[4];
#pragma unroll
            for (int i = 0; i < 2; i++) {
                wmma::load_matrix_sync(ah[i], &Ah[wm * 32 + i * 16][ks], 40);
                wmma::load_matrix_sync(al[i], &Al[wm * 32 + i * 16][ks], 40);
            }
#pragma unroll
            for (int j = 0; j < 4; j++) {
                wmma::load_matrix_sync(bh[j], &Bh[ks][wn * 64 + j * 16], 136);
                wmma::load_matrix_sync(bl[j], &Bl[ks][wn * 64 + j * 16], 136);
            }
#pragma unroll
            for (int i = 0; i < 2; i++)
#pragma unroll
                for (int j = 0; j < 4; j++) {
                    wmma::mma_sync(acc[i][j], ah[i], bl[j], acc[i][j]);
                    wmma::mma_sync(acc[i][j], al[i], bh[j], acc[i][j]);
                    wmma::mma_sync(acc[i][j], ah[i], bh[j], acc[i][j]);
                }
        }
    }

#pragma unroll
    for (int i = 0; i < 2; i++)
#pragma unroll
        for (int j = 0; j < 4; j++)
            wmma::store_matrix_sync(
                g_ctx + (size_t)(mBase + wm * 32 + i * 16) * (N_H * H_DIM)
                      + h * H_DIM + wn * 64 + j * 16,
                acc[i][j], N_H * H_DIM, wmma::mem_row_major);
}

// ===========================================================================
extern "C" void kernel_launch(void* const* d_in, const int* in_sizes, int n_in,
                              void* d_out, int out_size)
{
    const float* hs   = (const float*)d_in[0];
    const float* cosb = (const float*)d_in[1];
    const float* sinb = (const float*)d_in[2];
    const float* wq   = (const float*)d_in[3];
    const float* wk   = (const float*)d_in[4];
    const float* wv   = (const float*)d_in[5];
    const float* wo   = (const float*)d_in[6];
    float* out = (float*)d_out;

    float *qp, *kp, *vp, *cp, *ap;
    cudaGetSymbolAddress((void**)&qp, g_q);
    cudaGetSymbolAddress((void**)&kp, g_k);
    cudaGetSymbolAddress((void**)&vp, g_v);
    cudaGetSymbolAddress((void**)&cp, g_ctx);
    cudaGetSymbolAddress((void**)&ap, g_attn);

    bf16 *hsh, *hsl, *wqh, *wql, *wkh, *wkl, *wvh, *wvl, *woh, *wol;
    bf16 *qh, *ql, *kh, *kl, *vh, *vl, *cth, *ctl;
    cudaGetSymbolAddress((void**)&hsh, g_hsh); cudaGetSymbolAddress((void**)&hsl, g_hsl);
    cudaGetSymbolAddress((void**)&wqh, g_wqh); cudaGetSymbolAddress((void**)&wql, g_wql);
    cudaGetSymbolAddress((void**)&wkh, g_wkh); cudaGetSymbolAddress((void**)&wkl, g_wkl);
    cudaGetSymbolAddress((void**)&wvh, g_wvh); cudaGetSymbolAddress((void**)&wvl, g_wvl);
    cudaGetSymbolAddress((void**)&woh, g_woh); cudaGetSymbolAddress((void**)&wol, g_wol);
    cudaGetSymbolAddress((void**)&qh, g_qh);   cudaGetSymbolAddress((void**)&ql, g_ql);
    cudaGetSymbolAddress((void**)&kh, g_kh);   cudaGetSymbolAddress((void**)&kl, g_kl);
    cudaGetSymbolAddress((void**)&vh, g_vh);   cudaGetSymbolAddress((void**)&vl, g_vl);
    cudaGetSymbolAddress((void**)&cth, g_cth); cudaGetSymbolAddress((void**)&ctl, g_ctl);

    const size_t need = (size_t)S_LEN * D_MODEL + (size_t)N_H * S_LEN * S_LEN;
    float* attnBuf = ((size_t)out_size >= need) ? (out + (size_t)S_LEN * D_MODEL) : ap;

    cudaFuncSetAttribute(gemm_pre_kernel, cudaFuncAttributeMaxDynamicSharedMemorySize, GEMM_SMEM);
    cudaFuncSetAttribute(scores_pre_kernel, cudaFuncAttributeMaxDynamicSharedMemorySize, GEMM_SMEM);

    const int nBig = 2048 * 2048, nSml = 2048 * 512;

    // 0) pre-split inputs
    split_kernel<<<nBig / 1024, 256>>>(hs, hsh, hsl, nBig);
    split_kernel<<<nBig / 1024, 256>>>(wq, wqh, wql, nBig);
    split_kernel<<<nSml / 1024, 256>>>(wk, wkh, wkl, nSml);
    split_kernel<<<nSml / 1024, 256>>>(wv, wvh, wvl, nSml);
    split_kernel<<<nBig / 1024, 256>>>(wo, woh, wol, nBig);

    // 1) projections (pipelined split-bf16 tensor cores)
    gemm_pre_kernel<<<dim3(D_MODEL / 128, S_LEN / 128), 256, GEMM_SMEM>>>(hsh, hsl, wqh, wql, qp, D_MODEL, D_MODEL);
    gemm_pre_kernel<<<dim3(KV_DIM / 128, S_LEN / 128), 256, GEMM_SMEM>>>(hsh, hsl, wkh, wkl, kp, KV_DIM, D_MODEL);
    gemm_pre_kernel<<<dim3(KV_DIM / 128, S_LEN / 128), 256, GEMM_SMEM>>>(hsh, hsl, wvh, wvl, vp, KV_DIM, D_MODEL);

    // 2) RoPE + split (q, k); split v
    {
        int totQ = S_LEN * N_H * (H_DIM / 2);
        int totK = S_LEN * N_KV * (H_DIM / 2);
        rope_split_kernel<<<(totQ + 255) / 256, 256>>>(qp, cosb, sinb, N_H, qh, ql);
        rope_split_kernel<<<(totK + 255) / 256, 256>>>(kp, cosb, sinb, N_KV, kh, kl);
        split_kernel<<<nSml / 1024, 256>>>(vp, vh, vl, nSml);
    }

    // 3) causal scores
    scores_pre_kernel<<<dim3(S_LEN / 128, S_LEN / 128, N_H), 256, GEMM_SMEM>>>(attnBuf);

    // 4) entmax in place
    entmax_kernel<<<N_H * S_LEN, 256>>>(attnBuf);

    // 5) attn @ v -> ctx, then split ctx
    av_kernel<<<dim3(1, S_LEN / 128, N_H), 256>>>(attnBuf);
    split_kernel<<<nBig / 1024, 256>>>(cp, cth, ctl, nBig);

    // 6) out = ctx @ wo^T
    gemm_pre_kernel<<<dim3(D_MODEL / 128, S_LEN / 128), 256, GEMM_SMEM>>>(cth, ctl, woh, wol, out, D_MODEL, D_MODEL);
}